// round 16
// baseline (speedup 1.0000x reference)
#include <cuda_runtime.h>
#include <cuda_bf16.h>
#include <cstdint>
#include <math.h>

#define NB 32
#define NT 1024
#define ND 256
#define NROWS (NB*NT)
#define M0 (1.0f/0.07f)
#define SP2 132    // sims: b32 stride per 128-col bf16x2 smem row (132%32==4)
#define ROWB 528   // sims: byte stride (SP2*4)
#define PSP 68     // proj: b32 stride per 128-col bf16 (64 u32 data + 4 pad)
#define PROWB 272  // proj: byte stride

// -------- scratch (device globals; zero-initialized, no allocation) --------
__device__ uint32_t g_eb[NROWS*ND/2];  // COMPRESSED e (normalized, x1/TEMP) bf16x2; row k = rank
__device__ uint32_t g_vb[NROWS*ND/2];  // COMPRESSED v
__device__ uint32_t g_wb[2*256*128];   // W as bf16x2: [z][row 256][c2 128]
__device__ int      g_rank[NROWS];     // rank per (b,t); last element + 1 = Tv
__device__ int      g_inv[NROWS];      // g_inv[b][k] = BATCH-LOCAL t with rank k (k < Tv)
__device__ float    g_pos[NROWS];      // banded positive max, compressed index
__device__ float    g_prs[NROWS*8];    // per (row, col-tile) partial expsums
__device__ float    g_pb[NB];          // per-batch mean loss

// ======================= helpers =======================
__device__ __forceinline__ uint32_t smem_u32(const void* p) {
    uint32_t a;
    asm("{ .reg .u64 t; cvta.to.shared.u64 t, %1; cvt.u32.u64 %0, t; }" : "=r"(a) : "l"(p));
    return a;
}
__device__ __forceinline__ void mma16(float* c, const uint32_t* a, const uint32_t* b) {
    asm volatile("mma.sync.aligned.m16n8k16.row.col.f32.bf16.bf16.f32 "
        "{%0,%1,%2,%3}, {%4,%5,%6,%7}, {%8,%9}, {%0,%1,%2,%3};"
        : "+f"(c[0]), "+f"(c[1]), "+f"(c[2]), "+f"(c[3])
        : "r"(a[0]), "r"(a[1]), "r"(a[2]), "r"(a[3]), "r"(b[0]), "r"(b[1]));
}
#define LDMX4(r, addr) \
    asm volatile("ldmatrix.sync.aligned.m8n8.x4.shared.b16 {%0,%1,%2,%3}, [%4];" \
        : "=r"((r)[0]), "=r"((r)[1]), "=r"((r)[2]), "=r"((r)[3]) : "r"(addr))
__device__ __forceinline__ void cpa16(uint32_t dst, const void* src) {
    asm volatile("cp.async.cg.shared.global [%0], [%1], 16;" :: "r"(dst), "l"(src) : "memory");
}
__device__ __forceinline__ float qsum(float v) {
    v += __shfl_xor_sync(0xffffffffu, v, 1);
    v += __shfl_xor_sync(0xffffffffu, v, 2);
    return v;
}
__device__ __forceinline__ uint32_t packbf2(float x, float y) {
    __nv_bfloat162 h = __floats2bfloat162_rn(x, y);
    return *reinterpret_cast<uint32_t*>(&h);
}
__device__ __forceinline__ float dotbf(uint32_t a, uint32_t b) {
    float2 fa = __bfloat1622float2(*reinterpret_cast<__nv_bfloat162*>(&a));
    float2 fb = __bfloat1622float2(*reinterpret_cast<__nv_bfloat162*>(&b));
    return fa.x * fb.x + fa.y * fb.y;
}

// ======================= kernel 1: rank scan (ballot) + inverse table + W bf16 preconvert =======================
__global__ void rank_kernel(const int* __restrict__ mask,
                            const float* __restrict__ Weeg, const float* __restrict__ Weye) {
    __shared__ int wincl[32], wex[32];
    const int b = blockIdx.x, t = threadIdx.x;   // 1024 threads
    const int w = t >> 5, lane = t & 31;
    const int val = (mask[b * NT + t] > 0) ? 1 : 0;
    const uint32_t bal = __ballot_sync(0xffffffffu, val);
    const int pre = __popc(bal & ((1u << lane) - 1u));
    if (lane == 0) wincl[w] = __popc(bal);

    // W preconvert: 32768 threads x 2 words cover 2*256*128 packed bf16x2
    const int gid = b * NT + t;
    #pragma unroll
    for (int j = 0; j < 2; ++j) {
        const int idx = gid * 2 + j;          // 0..65535
        const int z = idx >> 15;
        const int rem = idx & 32767;
        const float* W = z ? Weye : Weeg;
        const float2 wv = *reinterpret_cast<const float2*>(W + (size_t)rem * 2);
        g_wb[idx] = packbf2(wv.x, wv.y);
    }

    __syncthreads();
    if (w == 0) {
        int x = wincl[lane];
        const int orig = x;
        #pragma unroll
        for (int o = 1; o < 32; o <<= 1) {
            int y = __shfl_up_sync(0xffffffffu, x, o);
            if (lane >= o) x += y;
        }
        wex[lane] = x - orig;
    }
    __syncthreads();
    const int base = wex[w];
    g_rank[b * NT + t] = base + pre + val - 1;
    if (val) g_inv[b * NT + base + pre] = t;   // batch-LOCAL t
}

// ======================= kernel 2: proj + L2-normalize, COMPRESSED rows =======================
__global__ __launch_bounds__(512, 1)
void proj_kernel(const float* __restrict__ eeg, const float* __restrict__ eye) {
    extern __shared__ uint32_t smu[];
    __shared__ int sidx[128];
    uint32_t* A_s  = smu;                   // [128][PSP]
    uint32_t* W_s  = smu + 128 * PSP;       // [256][PSP]
    float* ssq_s   = reinterpret_cast<float*>(W_s + 256 * PSP);  // [128][4]
    const uint32_t sbA = smem_u32(smu);
    const uint32_t sbW = sbA + 128 * PROWB;
    const int tid = threadIdx.x, wid = tid >> 5, lane = tid & 31;
    const int g = lane >> 2, t = lane & 3;
    const int wm = wid >> 2, wn = wid & 3;
    const int bx = blockIdx.x;
    const int b = bx >> 3, kbase = (bx & 7) * 128;
    const int Tv = g_rank[b * NT + NT - 1] + 1;
    if (kbase >= Tv) return;
    const int z = blockIdx.y;
    const float* src = z ? eye : eeg;
    const uint32_t* wb = g_wb + z * 32768;
    uint32_t* dst    = z ? g_vb : g_eb;
    const float extra = z ? 1.0f : M0;

    if (tid < 128) sidx[tid] = g_inv[b * NT + min(kbase + tid, Tv - 1)];

    float acc[2][8][4];
    #pragma unroll
    for (int mt = 0; mt < 2; mt++)
        #pragma unroll
        for (int nt = 0; nt < 8; nt++)
            #pragma unroll
            for (int q = 0; q < 4; q++) acc[mt][nt][q] = 0.f;

    const uint32_t lrow = lane & 15, lkoff = (lane >> 4) * 16;
    const uint32_t aA0 = sbA + (wm * 32 + lrow) * PROWB + lkoff;
    const uint32_t aA1 = aA0 + 16 * PROWB;
    uint32_t bA[4];
    #pragma unroll
    for (int p = 0; p < 4; ++p)
        bA[p] = sbW + (wn * 64 + p * 16 + lrow) * PROWB + lkoff;

    __syncthreads();   // sidx visible
    #pragma unroll 1
    for (int kh = 0; kh < 2; ++kh) {
        if (kh) __syncthreads();
        // gathered A rows (128 x 128 fp32 -> bf16); GLOBAL row = b*NT + sidx[r]
        #pragma unroll 4
        for (int i = tid; i < 128 * 32; i += 512) {
            const int r = i >> 5, c4 = (i & 31) << 2;
            const float* srow = src + ((size_t)b * NT + sidx[r]) * ND + kh * 128;
            float4 v = *reinterpret_cast<const float4*>(srow + c4);
            uint2 o;
            o.x = packbf2(v.x, v.y);
            o.y = packbf2(v.z, v.w);
            *reinterpret_cast<uint2*>(A_s + r * PSP + (c4 >> 1)) = o;
        }
        // W rows from preconverted bf16 (pure uint4 copies)
        #pragma unroll 4
        for (int i = tid; i < 256 * 16; i += 512) {
            const int r = i >> 4, c = i & 15;
            uint4 v = *reinterpret_cast<const uint4*>(wb + r * 128 + kh * 64 + c * 4);
            *reinterpret_cast<uint4*>(W_s + r * PSP + c * 4) = v;
        }
        __syncthreads();
        #pragma unroll
        for (int ks = 0; ks < 8; ++ks) {
            const int kb = ks * 32;
            uint32_t a0[4], a1[4];
            LDMX4(a0, aA0 + kb);
            LDMX4(a1, aA1 + kb);
            #pragma unroll
            for (int p = 0; p < 4; ++p) {
                uint32_t r[4];
                LDMX4(r, bA[p] + kb);
                uint32_t b0[2] = { r[0], r[2] };
                uint32_t b1[2] = { r[1], r[3] };
                mma16(acc[0][2 * p + 0], a0, b0);
                mma16(acc[0][2 * p + 1], a0, b1);
                mma16(acc[1][2 * p + 0], a1, b0);
                mma16(acc[1][2 * p + 1], a1, b1);
            }
        }
    }
    __syncthreads();

    float ssq[2][2] = {{0.f, 0.f}, {0.f, 0.f}};
    #pragma unroll
    for (int mt = 0; mt < 2; ++mt)
        #pragma unroll
        for (int nt = 0; nt < 8; ++nt) {
            ssq[mt][0] = fmaf(acc[mt][nt][0], acc[mt][nt][0], ssq[mt][0]);
            ssq[mt][0] = fmaf(acc[mt][nt][1], acc[mt][nt][1], ssq[mt][0]);
            ssq[mt][1] = fmaf(acc[mt][nt][2], acc[mt][nt][2], ssq[mt][1]);
            ssq[mt][1] = fmaf(acc[mt][nt][3], acc[mt][nt][3], ssq[mt][1]);
        }
    #pragma unroll
    for (int mt = 0; mt < 2; ++mt)
        #pragma unroll
        for (int rg = 0; rg < 2; ++rg)
            ssq[mt][rg] = qsum(ssq[mt][rg]);
    if (t == 0) {
        #pragma unroll
        for (int mt = 0; mt < 2; ++mt)
            #pragma unroll
            for (int rg = 0; rg < 2; ++rg)
                ssq_s[(wm * 32 + mt * 16 + g + 8 * rg) * 4 + wn] = ssq[mt][rg];
    }
    __syncthreads();
    #pragma unroll
    for (int mt = 0; mt < 2; ++mt)
        #pragma unroll
        for (int rg = 0; rg < 2; ++rg) {
            const int row = wm * 32 + mt * 16 + g + 8 * rg;
            const float s = ssq_s[row * 4 + 0] + ssq_s[row * 4 + 1]
                          + ssq_s[row * 4 + 2] + ssq_s[row * 4 + 3];
            const float sc = extra / fmaxf(sqrtf(s), 1e-12f);
            uint32_t* orow = dst + (size_t)(bx * 128 + row) * (ND / 2) + wn * 32;
            #pragma unroll
            for (int nt = 0; nt < 8; ++nt)
                orow[nt * 4 + t] = packbf2(acc[mt][nt][2 * rg + 0] * sc,
                                           acc[mt][nt][2 * rg + 1] * sc);
        }
}

// ======================= kernel 3: banded positive max (compressed, dense reads) =======================
__global__ __launch_bounds__(256)
void pos_kernel() {
    const int wid = threadIdx.x >> 5, lane = threadIdx.x & 31;
    const int gr = blockIdx.x * 8 + wid;      // compressed index b*NT + k
    const int b = gr >> 10, k = gr & (NT - 1);
    const int Tv = g_rank[b * NT + NT - 1] + 1;
    if (k >= Tv) return;
    const int lo = max(0, k - 2), hi = min(Tv - 1, k + 2);
    const uint4 ev = reinterpret_cast<const uint4*>(g_eb + (size_t)gr * 128)[lane];
    float pm = -1e30f;
    for (int j = lo; j <= hi; ++j) {
        const uint4 vv = reinterpret_cast<const uint4*>(g_vb + (size_t)(b * NT + j) * 128)[lane];
        float s = dotbf(ev.x, vv.x) + dotbf(ev.y, vv.y)
                + dotbf(ev.z, vv.z) + dotbf(ev.w, vv.w);
        #pragma unroll
        for (int o = 16; o > 0; o >>= 1) s += __shfl_xor_sync(0xffffffffu, s, o);
        pm = fmaxf(pm, s);
    }
    if (lane == 0) g_pos[gr] = pm;
}

// ======================= kernel 4: sims — single 64x128 tile per block, 2 CTAs/SM =======================
// Block (rt, ct): rows [rt*64, +64), cols [ct*128, +128) in compressed space.
// Writes additive partial expsum per row to g_prs[row][ct]; comb_kernel finishes.
__global__ __launch_bounds__(256, 2)
void sims_kernel() {
    extern __shared__ char smc[];
    uint32_t* E2  = reinterpret_cast<uint32_t*>(smc);   // 64 x SP2
    uint32_t* V2  = E2 + 64 * SP2;                      // 128 x SP2
    float*    mrg = reinterpret_cast<float*>(V2 + 128 * SP2);  // [64][4]
    const uint32_t sbE = smem_u32(smc);
    const uint32_t sbV = sbE + 64 * ROWB;

    const int tid = threadIdx.x, wid = tid >> 5, lane = tid & 31;
    const int g = lane >> 2, t = lane & 3;
    const int wm = wid >> 2, wn = wid & 3;            // 2 x 4 warps
    const int b = blockIdx.y;
    const int rt = blockIdx.x >> 3, ct = blockIdx.x & 7;
    const int rbase = rt * 64, jbase = ct * 128;
    const int Tv = g_rank[b * NT + NT - 1] + 1;
    if (rbase >= Tv || jbase >= Tv) return;

    const char* ebase = reinterpret_cast<const char*>(g_eb) + (size_t)b * NT * 512;
    const char* vbase = reinterpret_cast<const char*>(g_vb) + (size_t)b * NT * 512;
    #pragma unroll 4
    for (int i = tid; i < 2048; i += 256) {
        const int r = i >> 5, ch = i & 31;
        cpa16(sbE + r * ROWB + ch * 16, ebase + (size_t)(rbase + r) * 512 + ch * 16);
    }
    #pragma unroll 4
    for (int i = tid; i < 4096; i += 256) {
        const int r = i >> 5, ch = i & 31;
        cpa16(sbV + r * ROWB + ch * 16, vbase + (size_t)(jbase + r) * 512 + ch * 16);
    }
    asm volatile("cp.async.commit_group;" ::: "memory");
    asm volatile("cp.async.wait_group 0;" ::: "memory");
    __syncthreads();

    const uint32_t lrow = lane & 15, lkoff = (lane >> 4) * 16;
    const uint32_t aA0 = sbE + (wm * 32 + lrow) * ROWB + lkoff;
    const uint32_t aA1 = aA0 + 16 * ROWB;
    const uint32_t bA0 = sbV + (wn * 32 + lrow) * ROWB + lkoff;
    const uint32_t bA1 = bA0 + 16 * ROWB;

    float acc[2][4][4];
    #pragma unroll
    for (int mt = 0; mt < 2; mt++)
        #pragma unroll
        for (int nt = 0; nt < 4; nt++)
            #pragma unroll
            for (int q = 0; q < 4; q++) acc[mt][nt][q] = 0.f;

    #pragma unroll
    for (int ks = 0; ks < 16; ++ks) {
        const int kb = ks * 32;
        uint32_t a0[4], a1[4], r0[4], r1[4];
        LDMX4(a0, aA0 + kb);
        LDMX4(a1, aA1 + kb);
        LDMX4(r0, bA0 + kb);
        LDMX4(r1, bA1 + kb);
        uint32_t b0[2] = { r0[0], r0[2] };
        uint32_t b1[2] = { r0[1], r0[3] };
        uint32_t b2[2] = { r1[0], r1[2] };
        uint32_t b3[2] = { r1[1], r1[3] };
        mma16(acc[0][0], a0, b0); mma16(acc[0][1], a0, b1);
        mma16(acc[0][2], a0, b2); mma16(acc[0][3], a0, b3);
        mma16(acc[1][0], a1, b0); mma16(acc[1][1], a1, b1);
        mma16(acc[1][2], a1, b2); mma16(acc[1][3], a1, b3);
    }

    // epilogue: biased exp-accumulate (validity = col < Tv in compressed space)
    float rs[2][2] = {{0.f, 0.f}, {0.f, 0.f}};
    #pragma unroll
    for (int nt = 0; nt < 4; ++nt)
        #pragma unroll
        for (int h = 0; h < 2; ++h) {
            const int col = jbase + wn * 32 + nt * 8 + 2 * t + h;
            const float cbv = (col < Tv) ? -M0 : -1e30f;
            rs[0][0] += __expf(acc[0][nt][h]     + cbv);
            rs[0][1] += __expf(acc[0][nt][2 + h] + cbv);
            rs[1][0] += __expf(acc[1][nt][h]     + cbv);
            rs[1][1] += __expf(acc[1][nt][2 + h] + cbv);
        }
    #pragma unroll
    for (int mt = 0; mt < 2; ++mt)
        #pragma unroll
        for (int rg = 0; rg < 2; ++rg) {
            const float s = qsum(rs[mt][rg]);
            if (t == 0)
                mrg[(wm * 32 + mt * 16 + g + 8 * rg) * 4 + wn] = s;
        }
    __syncthreads();
    if (tid < 64) {
        const float s = mrg[tid * 4 + 0] + mrg[tid * 4 + 1]
                      + mrg[tid * 4 + 2] + mrg[tid * 4 + 3];
        g_prs[((size_t)b * NT + rbase + tid) * 8 + ct] = s;
    }
}

// ======================= kernel 5: combine partials -> per-row loss -> per-batch mean =======================
__global__ void comb_kernel() {
    __shared__ float sbuf[32];
    const int b = blockIdx.x, tid = threadIdx.x;   // 1024 threads
    const int w = tid >> 5, lane = tid & 31;
    const int Tv = g_rank[b * NT + NT - 1] + 1;
    const int nct = (Tv + 127) >> 7;
    float rl = 0.f;
    if (tid < Tv) {
        float s = 0.f;
        const float* p = g_prs + ((size_t)b * NT + tid) * 8;
        for (int ct = 0; ct < nct; ++ct) s += p[ct];
        rl = (M0 + logf(s)) - g_pos[b * NT + tid];   // lse - posmax
    }
    #pragma unroll
    for (int o = 16; o > 0; o >>= 1) rl += __shfl_xor_sync(0xffffffffu, rl, o);
    if (lane == 0) sbuf[w] = rl;
    __syncthreads();
    if (tid == 0) {
        float tot = 0.f;
        #pragma unroll
        for (int i = 0; i < 32; i++) tot += sbuf[i];
        g_pb[b] = (Tv >= 2) ? (tot / (float)Tv) : 0.f;
    }
}

// ======================= kernel 6: final scalar =======================
__global__ void fin_kernel(float* __restrict__ out) {
    float v = g_pb[threadIdx.x];
    #pragma unroll
    for (int o = 16; o > 0; o >>= 1) v += __shfl_xor_sync(0xffffffffu, v, o);
    if (threadIdx.x == 0) out[0] = v / (32.0f + 1e-8f);
}

extern "C" void kernel_launch(void* const* d_in, const int* in_sizes, int n_in,
                              void* d_out, int out_size) {
    const float* eeg  = (const float*)d_in[0];
    const float* eye  = (const float*)d_in[1];
    const int*   mask = (const int*)d_in[2];
    const float* Weeg = (const float*)d_in[3];
    const float* Weye = (const float*)d_in[4];
    float* out = (float*)d_out;

    const int PROJ_SMEM = (128 * PSP + 256 * PSP) * 4 + 128 * 4 * 4;   // 106496 B
    const int SIMS_SMEM = (64 + 128) * ROWB + 64 * 4 * 4;              // 102400 B

    cudaFuncSetAttribute(proj_kernel, cudaFuncAttributeMaxDynamicSharedMemorySize, PROJ_SMEM);
    cudaFuncSetAttribute(sims_kernel, cudaFuncAttributeMaxDynamicSharedMemorySize, SIMS_SMEM);

    // 6 launches; sims stays in capture slot #4.
    rank_kernel<<<NB, NT>>>(mask, Weeg, Weye);
    proj_kernel<<<dim3(NROWS / 128, 2), 512, PROJ_SMEM>>>(eeg, eye);
    pos_kernel<<<NROWS / 8, 256>>>();
    sims_kernel<<<dim3(128, NB), 256, SIMS_SMEM>>>();
    comb_kernel<<<NB, NT>>>();
    fin_kernel<<<1, 32>>>(out);
}

// round 17
// speedup vs baseline: 1.0615x; 1.0615x over previous
#include <cuda_runtime.h>
#include <cuda_bf16.h>
#include <cstdint>
#include <math.h>

#define NB 32
#define NT 1024
#define ND 256
#define NROWS (NB*NT)
#define M0 (1.0f/0.07f)
#define SP2 132    // sims: b32 stride per 128-col bf16x2 smem row (132%32==4)
#define ROWB 528   // sims: byte stride (SP2*4)
#define PSP 68     // proj: b32 stride per 128-col bf16 (64 u32 data + 4 pad)
#define PROWB 272  // proj: byte stride

// -------- scratch (device globals; zero-initialized, no allocation) --------
__device__ uint32_t g_eb[NROWS*ND/2];  // COMPRESSED e (normalized, x1/TEMP) bf16x2; row k = rank
__device__ uint32_t g_vb[NROWS*ND/2];  // COMPRESSED v
__device__ uint32_t g_wb[2*256*128];   // W as bf16x2: [z][row 256][c2 128]
__device__ int      g_rank[NROWS];     // rank per (b,t); last element + 1 = Tv
__device__ int      g_inv[NROWS];      // g_inv[b][k] = BATCH-LOCAL t with rank k (k < Tv)
__device__ float    g_pos[NROWS];      // banded positive max, compressed index
__device__ float    g_ps[NB*8];        // per sims-block partial loss sums

// ======================= helpers =======================
__device__ __forceinline__ uint32_t smem_u32(const void* p) {
    uint32_t a;
    asm("{ .reg .u64 t; cvta.to.shared.u64 t, %1; cvt.u32.u64 %0, t; }" : "=r"(a) : "l"(p));
    return a;
}
__device__ __forceinline__ void mma16(float* c, const uint32_t* a, const uint32_t* b) {
    asm volatile("mma.sync.aligned.m16n8k16.row.col.f32.bf16.bf16.f32 "
        "{%0,%1,%2,%3}, {%4,%5,%6,%7}, {%8,%9}, {%0,%1,%2,%3};"
        : "+f"(c[0]), "+f"(c[1]), "+f"(c[2]), "+f"(c[3])
        : "r"(a[0]), "r"(a[1]), "r"(a[2]), "r"(a[3]), "r"(b[0]), "r"(b[1]));
}
#define LDMX4(r, addr) \
    asm volatile("ldmatrix.sync.aligned.m8n8.x4.shared.b16 {%0,%1,%2,%3}, [%4];" \
        : "=r"((r)[0]), "=r"((r)[1]), "=r"((r)[2]), "=r"((r)[3]) : "r"(addr))
__device__ __forceinline__ void cpa16(uint32_t dst, const void* src) {
    asm volatile("cp.async.cg.shared.global [%0], [%1], 16;" :: "r"(dst), "l"(src) : "memory");
}
__device__ __forceinline__ float qsum(float v) {
    v += __shfl_xor_sync(0xffffffffu, v, 1);
    v += __shfl_xor_sync(0xffffffffu, v, 2);
    return v;
}
__device__ __forceinline__ uint32_t packbf2(float x, float y) {
    __nv_bfloat162 h = __floats2bfloat162_rn(x, y);
    return *reinterpret_cast<uint32_t*>(&h);
}
__device__ __forceinline__ float dotbf(uint32_t a, uint32_t b) {
    float2 fa = __bfloat1622float2(*reinterpret_cast<__nv_bfloat162*>(&a));
    float2 fb = __bfloat1622float2(*reinterpret_cast<__nv_bfloat162*>(&b));
    return fa.x * fb.x + fa.y * fb.y;
}

// ======================= kernel 1: rank scan (ballot) + inverse table + W bf16 preconvert =======================
__global__ void rank_kernel(const int* __restrict__ mask,
                            const float* __restrict__ Weeg, const float* __restrict__ Weye) {
    __shared__ int wincl[32], wex[32];
    const int b = blockIdx.x, t = threadIdx.x;   // 1024 threads
    const int w = t >> 5, lane = t & 31;
    const int val = (mask[b * NT + t] > 0) ? 1 : 0;
    const uint32_t bal = __ballot_sync(0xffffffffu, val);
    const int pre = __popc(bal & ((1u << lane) - 1u));
    if (lane == 0) wincl[w] = __popc(bal);

    // W preconvert: 32768 threads x 2 words cover 2*256*128 packed bf16x2
    const int gid = b * NT + t;
    #pragma unroll
    for (int j = 0; j < 2; ++j) {
        const int idx = gid * 2 + j;          // 0..65535
        const int z = idx >> 15;
        const int rem = idx & 32767;
        const float* W = z ? Weye : Weeg;
        const float2 wv = *reinterpret_cast<const float2*>(W + (size_t)rem * 2);
        g_wb[idx] = packbf2(wv.x, wv.y);
    }

    __syncthreads();
    if (w == 0) {
        int x = wincl[lane];
        const int orig = x;
        #pragma unroll
        for (int o = 1; o < 32; o <<= 1) {
            int y = __shfl_up_sync(0xffffffffu, x, o);
            if (lane >= o) x += y;
        }
        wex[lane] = x - orig;
    }
    __syncthreads();
    const int base = wex[w];
    g_rank[b * NT + t] = base + pre + val - 1;
    if (val) g_inv[b * NT + base + pre] = t;   // batch-LOCAL t
}

// ======================= kernel 2: proj + L2-normalize, COMPRESSED rows =======================
__global__ __launch_bounds__(512, 1)
void proj_kernel(const float* __restrict__ eeg, const float* __restrict__ eye) {
    extern __shared__ uint32_t smu[];
    __shared__ int sidx[128];
    uint32_t* A_s  = smu;                   // [128][PSP]
    uint32_t* W_s  = smu + 128 * PSP;       // [256][PSP]
    float* ssq_s   = reinterpret_cast<float*>(W_s + 256 * PSP);  // [128][4]
    const uint32_t sbA = smem_u32(smu);
    const uint32_t sbW = sbA + 128 * PROWB;
    const int tid = threadIdx.x, wid = tid >> 5, lane = tid & 31;
    const int g = lane >> 2, t = lane & 3;
    const int wm = wid >> 2, wn = wid & 3;
    const int bx = blockIdx.x;
    const int b = bx >> 3, kbase = (bx & 7) * 128;
    const int Tv = g_rank[b * NT + NT - 1] + 1;
    if (kbase >= Tv) return;
    const int z = blockIdx.y;
    const float* src = z ? eye : eeg;
    const uint32_t* wb = g_wb + z * 32768;
    uint32_t* dst    = z ? g_vb : g_eb;
    const float extra = z ? 1.0f : M0;

    if (tid < 128) sidx[tid] = g_inv[b * NT + min(kbase + tid, Tv - 1)];

    float acc[2][8][4];
    #pragma unroll
    for (int mt = 0; mt < 2; mt++)
        #pragma unroll
        for (int nt = 0; nt < 8; nt++)
            #pragma unroll
            for (int q = 0; q < 4; q++) acc[mt][nt][q] = 0.f;

    const uint32_t lrow = lane & 15, lkoff = (lane >> 4) * 16;
    const uint32_t aA0 = sbA + (wm * 32 + lrow) * PROWB + lkoff;
    const uint32_t aA1 = aA0 + 16 * PROWB;
    uint32_t bA[4];
    #pragma unroll
    for (int p = 0; p < 4; ++p)
        bA[p] = sbW + (wn * 64 + p * 16 + lrow) * PROWB + lkoff;

    __syncthreads();   // sidx visible
    #pragma unroll 1
    for (int kh = 0; kh < 2; ++kh) {
        if (kh) __syncthreads();
        // gathered A rows (128 x 128 fp32 -> bf16); GLOBAL row = b*NT + sidx[r]
        #pragma unroll 4
        for (int i = tid; i < 128 * 32; i += 512) {
            const int r = i >> 5, c4 = (i & 31) << 2;
            const float* srow = src + ((size_t)b * NT + sidx[r]) * ND + kh * 128;
            float4 v = *reinterpret_cast<const float4*>(srow + c4);
            uint2 o;
            o.x = packbf2(v.x, v.y);
            o.y = packbf2(v.z, v.w);
            *reinterpret_cast<uint2*>(A_s + r * PSP + (c4 >> 1)) = o;
        }
        // W rows from preconverted bf16 (pure uint4 copies)
        #pragma unroll 4
        for (int i = tid; i < 256 * 16; i += 512) {
            const int r = i >> 4, c = i & 15;
            uint4 v = *reinterpret_cast<const uint4*>(wb + r * 128 + kh * 64 + c * 4);
            *reinterpret_cast<uint4*>(W_s + r * PSP + c * 4) = v;
        }
        __syncthreads();
        #pragma unroll
        for (int ks = 0; ks < 8; ++ks) {
            const int kb = ks * 32;
            uint32_t a0[4], a1[4];
            LDMX4(a0, aA0 + kb);
            LDMX4(a1, aA1 + kb);
            #pragma unroll
            for (int p = 0; p < 4; ++p) {
                uint32_t r[4];
                LDMX4(r, bA[p] + kb);
                uint32_t b0[2] = { r[0], r[2] };
                uint32_t b1[2] = { r[1], r[3] };
                mma16(acc[0][2 * p + 0], a0, b0);
                mma16(acc[0][2 * p + 1], a0, b1);
                mma16(acc[1][2 * p + 0], a1, b0);
                mma16(acc[1][2 * p + 1], a1, b1);
            }
        }
    }
    __syncthreads();

    float ssq[2][2] = {{0.f, 0.f}, {0.f, 0.f}};
    #pragma unroll
    for (int mt = 0; mt < 2; ++mt)
        #pragma unroll
        for (int nt = 0; nt < 8; ++nt) {
            ssq[mt][0] = fmaf(acc[mt][nt][0], acc[mt][nt][0], ssq[mt][0]);
            ssq[mt][0] = fmaf(acc[mt][nt][1], acc[mt][nt][1], ssq[mt][0]);
            ssq[mt][1] = fmaf(acc[mt][nt][2], acc[mt][nt][2], ssq[mt][1]);
            ssq[mt][1] = fmaf(acc[mt][nt][3], acc[mt][nt][3], ssq[mt][1]);
        }
    #pragma unroll
    for (int mt = 0; mt < 2; ++mt)
        #pragma unroll
        for (int rg = 0; rg < 2; ++rg)
            ssq[mt][rg] = qsum(ssq[mt][rg]);
    if (t == 0) {
        #pragma unroll
        for (int mt = 0; mt < 2; ++mt)
            #pragma unroll
            for (int rg = 0; rg < 2; ++rg)
                ssq_s[(wm * 32 + mt * 16 + g + 8 * rg) * 4 + wn] = ssq[mt][rg];
    }
    __syncthreads();
    #pragma unroll
    for (int mt = 0; mt < 2; ++mt)
        #pragma unroll
        for (int rg = 0; rg < 2; ++rg) {
            const int row = wm * 32 + mt * 16 + g + 8 * rg;
            const float s = ssq_s[row * 4 + 0] + ssq_s[row * 4 + 1]
                          + ssq_s[row * 4 + 2] + ssq_s[row * 4 + 3];
            const float sc = extra / fmaxf(sqrtf(s), 1e-12f);
            uint32_t* orow = dst + (size_t)(bx * 128 + row) * (ND / 2) + wn * 32;
            #pragma unroll
            for (int nt = 0; nt < 8; ++nt)
                orow[nt * 4 + t] = packbf2(acc[mt][nt][2 * rg + 0] * sc,
                                           acc[mt][nt][2 * rg + 1] * sc);
        }
}

// ======================= kernel 3: banded positive max (compressed, dense reads) =======================
__global__ __launch_bounds__(256)
void pos_kernel() {
    const int wid = threadIdx.x >> 5, lane = threadIdx.x & 31;
    const int gr = blockIdx.x * 8 + wid;      // compressed index b*NT + k
    const int b = gr >> 10, k = gr & (NT - 1);
    const int Tv = g_rank[b * NT + NT - 1] + 1;
    if (k >= Tv) return;
    const int lo = max(0, k - 2), hi = min(Tv - 1, k + 2);
    const uint4 ev = reinterpret_cast<const uint4*>(g_eb + (size_t)gr * 128)[lane];
    float pm = -1e30f;
    for (int j = lo; j <= hi; ++j) {
        const uint4 vv = reinterpret_cast<const uint4*>(g_vb + (size_t)(b * NT + j) * 128)[lane];
        float s = dotbf(ev.x, vv.x) + dotbf(ev.y, vv.y)
                + dotbf(ev.z, vv.z) + dotbf(ev.w, vv.w);
        #pragma unroll
        for (int o = 16; o > 0; o >>= 1) s += __shfl_xor_sync(0xffffffffu, s, o);
        pm = fmaxf(pm, s);
    }
    if (lane == 0) g_pos[gr] = pm;
}

// ======================= kernel 4: sims over compressed rows (R15 structure) + partial sums =======================
__global__ __launch_bounds__(512, 1)
void sims_kernel() {
    extern __shared__ char smc[];
    uint32_t* E2  = reinterpret_cast<uint32_t*>(smc);              // 128 x SP2
    uint32_t* V2  = E2 + 128 * SP2;                                // 2 x 128 x SP2
    float*    cb  = reinterpret_cast<float*>(V2 + 2 * 128 * SP2);  // [1024]
    float*    mrg = cb + NT;                                       // [128][4]
    float*    sred = mrg + 128 * 4;                                // [4]
    const uint32_t sbE = smem_u32(smc);
    const uint32_t sbV = sbE + 128 * ROWB;

    const int tid = threadIdx.x, wid = tid >> 5, lane = tid & 31;
    const int g = lane >> 2, t = lane & 3;
    const int wm = wid >> 2, wn = wid & 3;
    const int b = blockIdx.y, rbase = blockIdx.x * 128;
    const int Tv = g_rank[b * NT + NT - 1] + 1;
    if (rbase >= Tv) {
        if (tid == 0) g_ps[b * 8 + blockIdx.x] = 0.f;
        return;
    }
    const int nct = (Tv + 127) >> 7;

    for (int i = tid; i < NT; i += 512)
        cb[i] = (i < Tv) ? -M0 : -1e30f;
    const char* ebase = reinterpret_cast<const char*>(g_eb) + (size_t)b * NT * 512;
    const char* vbase = reinterpret_cast<const char*>(g_vb) + (size_t)b * NT * 512;
    #pragma unroll 4
    for (int i = tid; i < 4096; i += 512) {
        const int r = i >> 5, ch = i & 31;
        cpa16(sbE + r * ROWB + ch * 16, ebase + (size_t)(rbase + r) * 512 + ch * 16);
    }
    #pragma unroll 4
    for (int i = tid; i < 4096; i += 512) {
        const int r = i >> 5, ch = i & 31;
        cpa16(sbV + r * ROWB + ch * 16, vbase + (size_t)r * 512 + ch * 16);
    }
    asm volatile("cp.async.commit_group;" ::: "memory");

    float rs[2][2] = {{0.f, 0.f}, {0.f, 0.f}};

    const uint32_t lrow = lane & 15, lkoff = (lane >> 4) * 16;
    const uint32_t aA0 = sbE + (wm * 32 + lrow) * ROWB + lkoff;  // mt=0
    const uint32_t aA1 = aA0 + 16 * ROWB;                        // mt=1

    #pragma unroll 1
    for (int jt = 0; jt < nct; ++jt) {
        asm volatile("cp.async.wait_group 0;" ::: "memory");
        __syncthreads();
        if (jt + 1 < nct) {
            const int jb2 = (jt + 1) * 128;
            const uint32_t vdst = sbV + ((jt + 1) & 1) * 128 * ROWB;
            #pragma unroll 4
            for (int i = tid; i < 4096; i += 512) {
                const int r = i >> 5, ch = i & 31;
                cpa16(vdst + r * ROWB + ch * 16,
                      vbase + (size_t)(jb2 + r) * 512 + ch * 16);
            }
            asm volatile("cp.async.commit_group;" ::: "memory");
        }
        float acc[2][4][4];
        #pragma unroll
        for (int mt = 0; mt < 2; mt++)
            #pragma unroll
            for (int nt = 0; nt < 4; nt++)
                #pragma unroll
                for (int q = 0; q < 4; q++) acc[mt][nt][q] = 0.f;

        const uint32_t vb = sbV + (jt & 1) * 128 * ROWB;
        uint32_t bA[2];
        #pragma unroll
        for (int p = 0; p < 2; ++p)
            bA[p] = vb + (wn * 32 + p * 16 + lrow) * ROWB + lkoff;

        #pragma unroll
        for (int ks = 0; ks < 16; ++ks) {
            const int kb = ks * 32;
            uint32_t a0[4], a1[4];
            LDMX4(a0, aA0 + kb);
            LDMX4(a1, aA1 + kb);
            #pragma unroll
            for (int p = 0; p < 2; ++p) {
                uint32_t r[4];
                LDMX4(r, bA[p] + kb);
                uint32_t b0[2] = { r[0], r[2] };
                uint32_t b1[2] = { r[1], r[3] };
                mma16(acc[0][2 * p + 0], a0, b0);
                mma16(acc[0][2 * p + 1], a0, b1);
                mma16(acc[1][2 * p + 0], a1, b0);
                mma16(acc[1][2 * p + 1], a1, b1);
            }
        }

        // epilogue: pure biased exp-accumulate
        const float* cbt = cb + jt * 128 + wn * 32 + 2 * t;
        #pragma unroll
        for (int nt = 0; nt < 4; ++nt)
            #pragma unroll
            for (int h = 0; h < 2; ++h) {
                const float cbv = cbt[nt * 8 + h];
                rs[0][0] += __expf(acc[0][nt][h]     + cbv);
                rs[0][1] += __expf(acc[0][nt][2 + h] + cbv);
                rs[1][0] += __expf(acc[1][nt][h]     + cbv);
                rs[1][1] += __expf(acc[1][nt][2 + h] + cbv);
            }
    }

    // deferred reductions -> per-row loss -> block partial sum
    #pragma unroll
    for (int mt = 0; mt < 2; ++mt)
        #pragma unroll
        for (int rg = 0; rg < 2; ++rg) {
            const float s = qsum(rs[mt][rg]);
            if (t == 0)
                mrg[(wm * 32 + mt * 16 + g + 8 * rg) * 4 + wn] = s;
        }
    __syncthreads();
    float rl = 0.f;
    if (tid < 128 && rbase + tid < Tv) {
        const float s = mrg[tid * 4 + 0] + mrg[tid * 4 + 1]
                      + mrg[tid * 4 + 2] + mrg[tid * 4 + 3];
        rl = (M0 + logf(s)) - g_pos[b * NT + rbase + tid];   // lse - posmax
    }
    if (tid < 128) {
        #pragma unroll
        for (int o = 16; o > 0; o >>= 1) rl += __shfl_xor_sync(0xffffffffu, rl, o);
        if (lane == 0) sred[wid] = rl;
    }
    __syncthreads();
    if (tid == 0)
        g_ps[b * 8 + blockIdx.x] = sred[0] + sred[1] + sred[2] + sred[3];
}

// ======================= kernel 5: final reduction =======================
__global__ void fin_kernel(float* __restrict__ out) {
    __shared__ float pb[32];
    const int t = threadIdx.x;   // 256
    const int lane = t & 31;
    float v = g_ps[t];
    v += __shfl_xor_sync(0xffffffffu, v, 1);
    v += __shfl_xor_sync(0xffffffffu, v, 2);
    v += __shfl_xor_sync(0xffffffffu, v, 4);
    if ((lane & 7) == 0) {
        const int b = t >> 3;
        const int Tv = g_rank[b * NT + NT - 1] + 1;
        pb[b] = (Tv >= 2) ? (v / (float)Tv) : 0.f;
    }
    __syncthreads();
    if (t == 0) {
        float tot = 0.f;
        #pragma unroll
        for (int i = 0; i < 32; i++) tot += pb[i];
        out[0] = tot / (32.0f + 1e-8f);
    }
}

extern "C" void kernel_launch(void* const* d_in, const int* in_sizes, int n_in,
                              void* d_out, int out_size) {
    const float* eeg  = (const float*)d_in[0];
    const float* eye  = (const float*)d_in[1];
    const int*   mask = (const int*)d_in[2];
    const float* Weeg = (const float*)d_in[3];
    const float* Weye = (const float*)d_in[4];
    float* out = (float*)d_out;

    const int PROJ_SMEM = (128 * PSP + 256 * PSP) * 4 + 128 * 4 * 4;            // 106496 B
    const int SIMS_SMEM = 3 * 128 * SP2 * 4 + NT * 4 + 128 * 4 * 4 + 4 * 4;     // 208912 B

    cudaFuncSetAttribute(proj_kernel, cudaFuncAttributeMaxDynamicSharedMemorySize, PROJ_SMEM);
    cudaFuncSetAttribute(sims_kernel, cudaFuncAttributeMaxDynamicSharedMemorySize, SIMS_SMEM);

    // 5 launches; sims stays in capture slot #4.
    rank_kernel<<<NB, NT>>>(mask, Weeg, Weye);
    proj_kernel<<<dim3(NROWS / 128, 2), 512, PROJ_SMEM>>>(eeg, eye);
    pos_kernel<<<NROWS / 8, 256>>>();
    sims_kernel<<<dim3(NT / 128, NB), 512, SIMS_SMEM>>>();
    fin_kernel<<<1, 256>>>(out);
}